// round 11
// baseline (speedup 1.0000x reference)
#include <cuda_runtime.h>
#include <cstdint>
#include <cstddef>

#define N_TOKENS   16384
#define IN_F       1024
#define OUT_F      1024
#define BH         32
#define BW         32
#define NB         256
#define N_RB       (OUT_F / BH)   // 32
#define TOK_TILE   256
#define THREADS    256
#define SMAX       16             // W blocks per smem chunk (32KB of uint4 frags)
#define QMAX       8128.0f        // |q| <= 8128 so q_hi fits int8 after round-split

__device__ int g_cnt[N_RB];
__device__ int g_blk[N_RB][NB];
__device__ int g_col[N_RB][NB];
__device__ int g_rbmap[N_RB];
__device__ unsigned g_amax_x_u, g_amax_w_u;
__device__ float g_Sx, g_inv;
__device__ uint4 g_wq[NB * 4 * 32];   // [b][nt][lane] = {b0hi,b1hi,b0lo,b1lo} (512KB)

// ---- kernel 0: reset amax, compact block lists, LPT-sort row blocks ----
__global__ void spmm_prep_kernel(const int* __restrict__ brow,
                                 const int* __restrict__ bcol) {
    __shared__ int sr[NB];
    __shared__ int scnt[N_RB];
    const int b = threadIdx.x;
    if (b == 0) { g_amax_x_u = 0u; g_amax_w_u = 0u; }
    sr[b] = brow[b];
    __syncthreads();
    const int rb = sr[b];
    int pos = 0;
    for (int j = 0; j < b; ++j) pos += (sr[j] == rb);
    g_blk[rb][pos] = b;
    g_col[rb][pos] = bcol[b];
    if (b < N_RB) {
        int c = 0;
        for (int j = 0; j < NB; ++j) c += (sr[j] == b);
        g_cnt[b] = c;
        scnt[b] = c;
    }
    __syncthreads();
    if (b < N_RB) {
        // stable rank by count descending -> heavy row-blocks scheduled first
        int rank = 0;
        for (int j = 0; j < N_RB; ++j)
            rank += (scnt[j] > scnt[b]) || (scnt[j] == scnt[b] && j < b);
        g_rbmap[rank] = b;
    }
}

// ---- kernel 1: amax over x (blocks 0..1023) and w (blocks 1024..1039) ----
__global__ void spmm_amax_kernel(const float* __restrict__ x,
                                 const float* __restrict__ w) {
    const int bid = blockIdx.x;
    const float4* src;
    unsigned* dst;
    size_t base;
    if (bid < 1024) { src = (const float4*)x; dst = &g_amax_x_u; base = (size_t)bid * 4096; }
    else            { src = (const float4*)w; dst = &g_amax_w_u; base = (size_t)(bid - 1024) * 4096; }
    float m = 0.0f;
#pragma unroll
    for (int j = 0; j < 16; ++j) {
        const float4 v = src[base + threadIdx.x + j * 256];
        m = fmaxf(m, fmaxf(fmaxf(fabsf(v.x), fabsf(v.y)), fmaxf(fabsf(v.z), fabsf(v.w))));
    }
#pragma unroll
    for (int o = 16; o > 0; o >>= 1)
        m = fmaxf(m, __shfl_xor_sync(0xffffffffu, m, o));
    if ((threadIdx.x & 31) == 0)
        atomicMax(dst, __float_as_uint(m));
}

__device__ __forceinline__ unsigned pack4(int q0, int q1, int q2, int q3) {
    return (q0 & 0xff) | ((q1 & 0xff) << 8) | ((q2 & 0xff) << 16) | ((q3 & 0xff) << 24);
}
__device__ __forceinline__ void quant_split(float v, float S, int& qh, int& ql) {
    const int q = __float2int_rn(v * S);
    qh = (q + 32) >> 6;          // round-to-nearest split: qh in [-127,127]
    ql = q - (qh << 6);          // ql in [-32,31]
}

// ---- kernel 2: quantize + fragment-pack W; thread0 publishes scales ----
__global__ void spmm_quantw_kernel(const float* __restrict__ w) {
    const int b   = blockIdx.x;
    const int tid = threadIdx.x;        // 128 threads
    const float aw = fmaxf(__uint_as_float(g_amax_w_u), 1e-30f);
    const float Sw = QMAX / aw;
    if (b == 0 && tid == 0) {
        const float ax = fmaxf(__uint_as_float(g_amax_x_u), 1e-30f);
        const float Sx = QMAX / ax;
        g_Sx  = Sx;
        g_inv = 1.0f / (Sx * Sw);
    }
    const int nt   = tid >> 5;
    const int lane = tid & 31;
    const int g    = lane >> 2;
    const int c    = lane & 3;
    // B fragment: n-col = nt*8+g, phys k bytes 8c..8c+7 (k-permuted, matches A)
    const float* wr = w + (size_t)b * (BH * BW) + (nt * 8 + g) * BW + 8 * c;
    int qh[8], ql[8];
#pragma unroll
    for (int j = 0; j < 8; ++j) quant_split(wr[j], Sw, qh[j], ql[j]);
    g_wq[(b * 4 + nt) * 32 + lane] =
        make_uint4(pack4(qh[0], qh[1], qh[2], qh[3]),
                   pack4(qh[4], qh[5], qh[6], qh[7]),
                   pack4(ql[0], ql[1], ql[2], ql[3]),
                   pack4(ql[4], ql[5], ql[6], ql[7]));
}

__device__ __forceinline__ void mma_s8(int* d, const unsigned* a,
                                       unsigned b0, unsigned b1) {
    asm volatile(
        "mma.sync.aligned.m16n8k32.row.col.s32.s8.s8.s32 "
        "{%0,%1,%2,%3}, {%4,%5,%6,%7}, {%8,%9}, {%0,%1,%2,%3};"
        : "+r"(d[0]), "+r"(d[1]), "+r"(d[2]), "+r"(d[3])
        : "r"(a[0]), "r"(a[1]), "r"(a[2]), "r"(a[3]), "r"(b0), "r"(b1));
}

// ---- main: CTA = 256 tokens x one 32-wide row-block; 8 independent warps.
// int8 14-bit fixed point: x*w = (64*xh+xl)(64*wh+wl); acc_hh += xh*wh,
// acc_cr += xh*wl + xl*wh (both weight 64); ll dropped (error ~1e-4 rel).
// One m16n8k32 IMMA covers a whole 32-k block per (mt,nt,term): 24 MMAs/iter.
__global__ __launch_bounds__(THREADS, 2)
void spmm_main_kernel(const float* __restrict__ x,
                      const float* __restrict__ bias,
                      float* __restrict__ out) {
    __shared__ alignas(16) uint4 smB[SMAX * 4 * 32];   // 32 KB

    const int rb   = g_rbmap[blockIdx.y];
    const int tok0 = blockIdx.x * TOK_TILE;
    const int tid  = threadIdx.x;
    const int wid  = tid >> 5;
    const int lane = tid & 31;
    const int g    = lane >> 2;   // 0..7
    const int c    = lane & 3;    // 0..3

    const int cnt = g_cnt[rb];
    const float Sx = g_Sx;

    int hh[2][4][4], cr[2][4][4];
#pragma unroll
    for (int mt = 0; mt < 2; ++mt)
#pragma unroll
        for (int nt = 0; nt < 4; ++nt)
#pragma unroll
            for (int r = 0; r < 4; ++r) { hh[mt][nt][r] = 0; cr[mt][nt][r] = 0; }

    const float* xw = x + (size_t)(tok0 + wid * 32) * IN_F;

    int done = 0;
    while (done < cnt) {
        const int n = (cnt - done < SMAX) ? (cnt - done) : SMAX;

        __syncthreads();   // previous chunk fully consumed
        for (int t = tid; t < n * 128; t += THREADS) {
            const int ii = t >> 7;
            const int r  = t & 127;
            smB[ii * 128 + r] = g_wq[g_blk[rb][done + ii] * 128 + r];
        }
        __syncthreads();

        int li = (wid + (int)blockIdx.x) % n;
        for (int step = 0; step < n; ++step) {
            const float* xb = xw + g_col[rb][done + li] * BW;

            // A: 8 LDG.128 -> quantize+split+pack into s8 fragments
            unsigned ah[2][4], al[2][4];
#pragma unroll
            for (int mt = 0; mt < 2; ++mt)
#pragma unroll
                for (int a = 0; a < 2; ++a) {
                    const float* row = xb + (size_t)(mt * 16 + 8 * a + g) * IN_F + 8 * c;
                    const float4 u = *(const float4*)(row);
                    const float4 v = *(const float4*)(row + 4);
                    int qh[8], ql[8];
                    quant_split(u.x, Sx, qh[0], ql[0]);
                    quant_split(u.y, Sx, qh[1], ql[1]);
                    quant_split(u.z, Sx, qh[2], ql[2]);
                    quant_split(u.w, Sx, qh[3], ql[3]);
                    quant_split(v.x, Sx, qh[4], ql[4]);
                    quant_split(v.y, Sx, qh[5], ql[5]);
                    quant_split(v.z, Sx, qh[6], ql[6]);
                    quant_split(v.w, Sx, qh[7], ql[7]);
                    ah[mt][a]     = pack4(qh[0], qh[1], qh[2], qh[3]);
                    ah[mt][a + 2] = pack4(qh[4], qh[5], qh[6], qh[7]);
                    al[mt][a]     = pack4(ql[0], ql[1], ql[2], ql[3]);
                    al[mt][a + 2] = pack4(ql[4], ql[5], ql[6], ql[7]);
                }

            uint4 bv[4];
#pragma unroll
            for (int nt = 0; nt < 4; ++nt)
                bv[nt] = smB[(li * 4 + nt) * 32 + lane];

            // term-major: long RAW reuse distance
#pragma unroll
            for (int nt = 0; nt < 4; ++nt)
#pragma unroll
                for (int mt = 0; mt < 2; ++mt)
                    mma_s8(hh[mt][nt], ah[mt], bv[nt].x, bv[nt].y);
#pragma unroll
            for (int nt = 0; nt < 4; ++nt)
#pragma unroll
                for (int mt = 0; mt < 2; ++mt)
                    mma_s8(cr[mt][nt], ah[mt], bv[nt].z, bv[nt].w);
#pragma unroll
            for (int nt = 0; nt < 4; ++nt)
#pragma unroll
                for (int mt = 0; mt < 2; ++mt)
                    mma_s8(cr[mt][nt], al[mt], bv[nt].x, bv[nt].y);

            if (++li == n) li = 0;
        }
        done += n;
    }

    // ---- epilogue: dequant, add bias, store ----
    const float inv = g_inv;
    const float* bp = bias + rb * BH;
#pragma unroll
    for (int nt = 0; nt < 4; ++nt) {
        const float2 bvv = *(const float2*)(bp + nt * 8 + 2 * c);
#pragma unroll
        for (int mt = 0; mt < 2; ++mt) {
            const int row0 = tok0 + wid * 32 + mt * 16 + g;
            float2 o0, o1;
            o0.x = (4096.0f * (float)hh[mt][nt][0] + 64.0f * (float)cr[mt][nt][0]) * inv + bvv.x;
            o0.y = (4096.0f * (float)hh[mt][nt][1] + 64.0f * (float)cr[mt][nt][1]) * inv + bvv.y;
            o1.x = (4096.0f * (float)hh[mt][nt][2] + 64.0f * (float)cr[mt][nt][2]) * inv + bvv.x;
            o1.y = (4096.0f * (float)hh[mt][nt][3] + 64.0f * (float)cr[mt][nt][3]) * inv + bvv.y;
            *(float2*)(out + (size_t)row0       * OUT_F + rb * BH + nt * 8 + 2 * c) = o0;
            *(float2*)(out + (size_t)(row0 + 8) * OUT_F + rb * BH + nt * 8 + 2 * c) = o1;
        }
    }
}

extern "C" void kernel_launch(void* const* d_in, const int* in_sizes, int n_in,
                              void* d_out, int out_size) {
    (void)in_sizes; (void)n_in; (void)out_size;
    const float* x    = (const float*)d_in[0];
    const float* w    = (const float*)d_in[1];
    const float* bias = (const float*)d_in[2];
    const int*   brow = (const int*)d_in[3];
    const int*   bcol = (const int*)d_in[4];
    float* out = (float*)d_out;

    spmm_prep_kernel<<<1, NB>>>(brow, bcol);
    spmm_amax_kernel<<<1040, 256>>>(x, w);
    spmm_quantw_kernel<<<NB, 128>>>(w);
    dim3 grid(N_TOKENS / TOK_TILE, N_RB);
    spmm_main_kernel<<<grid, THREADS>>>(x, bias, out);
}

// round 12
// speedup vs baseline: 2.5570x; 2.5570x over previous
#include <cuda_runtime.h>
#include <cuda_fp16.h>
#include <cstdint>
#include <cstddef>

#define N_TOKENS   16384
#define IN_F       1024
#define OUT_F      1024
#define BH         32
#define BW         32
#define NB         256
#define N_RB       (OUT_F / BH)   // 32
#define TOK_TILE   256
#define THREADS    256
#define SMAX       12             // W blocks per smem chunk (48KB)

__device__ int g_cnt[N_RB];
__device__ int g_blk[N_RB][NB];
__device__ int g_col[N_RB][NB];
__device__ int g_rbmap[N_RB];
// [b][s][nt][lane] = uint4{bm0, bm1, br0, br1} (fp16x2 fragments), 4KB/block, 1MB
__device__ uint4 g_wq[NB * 2 * 4 * 32];

// ---- prep: compact block lists + LPT sort of row blocks ----
__global__ void spmm_prep_kernel(const int* __restrict__ brow,
                                 const int* __restrict__ bcol) {
    __shared__ int sr[NB];
    __shared__ int scnt[N_RB];
    const int b = threadIdx.x;
    sr[b] = brow[b];
    __syncthreads();
    const int rb = sr[b];
    int pos = 0;
    for (int j = 0; j < b; ++j) pos += (sr[j] == rb);
    g_blk[rb][pos] = b;
    g_col[rb][pos] = bcol[b];
    if (b < N_RB) {
        int c = 0;
        for (int j = 0; j < NB; ++j) c += (sr[j] == b);
        g_cnt[b] = c;
        scnt[b] = c;
    }
    __syncthreads();
    if (b < N_RB) {
        int rank = 0;
        for (int j = 0; j < N_RB; ++j)
            rank += (scnt[j] > scnt[b]) || (scnt[j] == scnt[b] && j < b);
        g_rbmap[rank] = b;
    }
}

// pack two floats -> fp16x2, LOWER-k element in LOW half.
__device__ __forceinline__ unsigned pack_f16(float hi, float lo) {
    unsigned d;
    asm("cvt.rn.f16x2.f32 %0, %1, %2;" : "=r"(d) : "f"(hi), "f"(lo));
    return d;
}

// ---- prep: quantize + fragment-pack W (main + residual fp16) ----
__global__ void spmm_quantw_kernel(const float* __restrict__ w) {
    const int b   = blockIdx.x;
    const int tid = threadIdx.x;        // 256 threads: one (s,nt,lane) each
    const int s    = tid >> 7;
    const int nt   = (tid >> 5) & 3;
    const int lane = tid & 31;
    const int g    = lane >> 2;
    const int c    = lane & 3;
    // fragment: n-col = nt*8+g, phys cols 16s + 4c .. 4c+3
    const float4 f = *(const float4*)
        (w + (size_t)b * (BH * BW) + (nt * 8 + g) * BW + 16 * s + 4 * c);
    const float mx = __half2float(__float2half_rn(f.x));
    const float my = __half2float(__float2half_rn(f.y));
    const float mz = __half2float(__float2half_rn(f.z));
    const float mw = __half2float(__float2half_rn(f.w));
    const unsigned bm0 = pack_f16(my, mx);
    const unsigned bm1 = pack_f16(mw, mz);
    const unsigned br0 = pack_f16(f.y - my, f.x - mx);
    const unsigned br1 = pack_f16(f.w - mw, f.z - mz);
    g_wq[((b * 2 + s) * 4 + nt) * 32 + lane] = make_uint4(bm0, bm1, br0, br1);
}

__device__ __forceinline__ void mma_f16(float* d, const unsigned* a,
                                        unsigned b0, unsigned b1) {
    asm volatile(
        "mma.sync.aligned.m16n8k16.row.col.f32.f16.f16.f32 "
        "{%0,%1,%2,%3}, {%4,%5,%6,%7}, {%8,%9}, {%0,%1,%2,%3};"
        : "+f"(d[0]), "+f"(d[1]), "+f"(d[2]), "+f"(d[3])
        : "r"(a[0]), "r"(a[1]), "r"(a[2]), "r"(a[3]), "r"(b0), "r"(b1));
}

// ---- main: CTA = 256 tokens x one 32-wide row-block; 8 independent warps.
// fp16 2-term: y = fp16(a) * (bm + br); dropped (a - fp16(a))*b ~ 2^-12 rel.
// 32 HMMA/warp-iter (vs 48 in bf16x3). W fragments pre-packed; A rounds with
// 16 cvt.rn.f16x2 in-loop. Rotated walk de-convoys warps between barriers.
__global__ __launch_bounds__(THREADS, 2)
void spmm_main_kernel(const float* __restrict__ x,
                      const float* __restrict__ bias,
                      float* __restrict__ out) {
    __shared__ alignas(16) uint4 smB[SMAX * 2 * 4 * 32];   // 48 KB

    const int rb   = g_rbmap[blockIdx.y];
    const int tok0 = blockIdx.x * TOK_TILE;
    const int tid  = threadIdx.x;
    const int wid  = tid >> 5;
    const int lane = tid & 31;
    const int g    = lane >> 2;   // 0..7
    const int c    = lane & 3;    // 0..3

    const int cnt = g_cnt[rb];

    float acc[2][4][4];
#pragma unroll
    for (int mt = 0; mt < 2; ++mt)
#pragma unroll
        for (int nt = 0; nt < 4; ++nt)
#pragma unroll
            for (int r = 0; r < 4; ++r) acc[mt][nt][r] = 0.0f;

    const float* xw = x + (size_t)(tok0 + wid * 32) * IN_F;

    int done = 0;
    while (done < cnt) {
        const int n = (cnt - done < SMAX) ? (cnt - done) : SMAX;

        __syncthreads();   // previous chunk fully consumed
        for (int t = tid; t < n * 256; t += THREADS) {
            const int ii = t >> 8;
            const int r  = t & 255;
            smB[ii * 256 + r] = g_wq[g_blk[rb][done + ii] * 256 + r];
        }
        __syncthreads();

        int li = (wid + (int)blockIdx.x) % n;
        for (int step = 0; step < n; ++step) {
            const float* xb = xw + g_col[rb][done + li] * BW;

            // A: 8 batched LDG.128; rows mt*16 + 8a + g, cols 16s + 4c
            float4 q[2][2][2];   // [mt][rowhalf a][s]
#pragma unroll
            for (int mt = 0; mt < 2; ++mt)
#pragma unroll
                for (int a = 0; a < 2; ++a)
#pragma unroll
                    for (int s = 0; s < 2; ++s)
                        q[mt][a][s] = *(const float4*)
                            (xb + (size_t)(mt * 16 + 8 * a + g) * IN_F + 16 * s + 4 * c);

#pragma unroll
            for (int s = 0; s < 2; ++s) {
                unsigned am[2][4];
#pragma unroll
                for (int mt = 0; mt < 2; ++mt) {
                    am[mt][0] = pack_f16(q[mt][0][s].y, q[mt][0][s].x);
                    am[mt][1] = pack_f16(q[mt][1][s].y, q[mt][1][s].x);
                    am[mt][2] = pack_f16(q[mt][0][s].w, q[mt][0][s].z);
                    am[mt][3] = pack_f16(q[mt][1][s].w, q[mt][1][s].z);
                }
                uint4 bv[4];
#pragma unroll
                for (int nt = 0; nt < 4; ++nt)
                    bv[nt] = smB[((li * 2 + s) * 4 + nt) * 32 + lane];

                // term-major: main term across all tiles, then residual term
#pragma unroll
                for (int nt = 0; nt < 4; ++nt)
#pragma unroll
                    for (int mt = 0; mt < 2; ++mt)
                        mma_f16(acc[mt][nt], am[mt], bv[nt].x, bv[nt].y);
#pragma unroll
                for (int nt = 0; nt < 4; ++nt)
#pragma unroll
                    for (int mt = 0; mt < 2; ++mt)
                        mma_f16(acc[mt][nt], am[mt], bv[nt].z, bv[nt].w);
            }

            if (++li == n) li = 0;
        }
        done += n;
    }

    // ---- epilogue: add bias, store ----
    const float* bp = bias + rb * BH;
#pragma unroll
    for (int nt = 0; nt < 4; ++nt) {
        const float2 bv = *(const float2*)(bp + nt * 8 + 2 * c);
#pragma unroll
        for (int mt = 0; mt < 2; ++mt) {
            const int row0 = tok0 + wid * 32 + mt * 16 + g;
            float2 o0, o1;
            o0.x = acc[mt][nt][0] + bv.x;
            o0.y = acc[mt][nt][1] + bv.y;
            o1.x = acc[mt][nt][2] + bv.x;
            o1.y = acc[mt][nt][3] + bv.y;
            *(float2*)(out + (size_t)row0       * OUT_F + rb * BH + nt * 8 + 2 * c) = o0;
            *(float2*)(out + (size_t)(row0 + 8) * OUT_F + rb * BH + nt * 8 + 2 * c) = o1;
        }
    }
}

extern "C" void kernel_launch(void* const* d_in, const int* in_sizes, int n_in,
                              void* d_out, int out_size) {
    (void)in_sizes; (void)n_in; (void)out_size;
    const float* x    = (const float*)d_in[0];
    const float* w    = (const float*)d_in[1];
    const float* bias = (const float*)d_in[2];
    const int*   brow = (const int*)d_in[3];
    const int*   bcol = (const int*)d_in[4];
    float* out = (float*)d_out;

    spmm_prep_kernel<<<1, NB>>>(brow, bcol);
    spmm_quantw_kernel<<<NB, 256>>>(w);
    dim3 grid(N_TOKENS / TOK_TILE, N_RB);
    spmm_main_kernel<<<grid, THREADS>>>(x, bias, out);
}

// round 13
// speedup vs baseline: 2.8267x; 1.1055x over previous
#include <cuda_runtime.h>
#include <cuda_fp16.h>
#include <cstdint>
#include <cstddef>

#define N_TOKENS   16384
#define IN_F       1024
#define OUT_F      1024
#define BH         32
#define BW         32
#define NB         256
#define N_RB       (OUT_F / BH)   // 32
#define TOK_TILE   256
#define THREADS    256
#define SMAX       24             // W blocks per smem chunk (48KB of uint2 frags)

__device__ int g_cnt[N_RB];
__device__ int g_blk[N_RB][NB];
__device__ int g_col[N_RB][NB];
__device__ int g_rbmap[N_RB];
// [b][s][nt][lane] = uint2{bm0, bm1} (fp16x2 fragments), 2KB/block, 512KB
__device__ uint2 g_wq[NB * 2 * 4 * 32];

// ---- prep: ballot-based stable compaction + LPT sort (replaces O(n^2) scan) ----
__global__ void spmm_prep_kernel(const int* __restrict__ brow,
                                 const int* __restrict__ bcol) {
    __shared__ int whist[8][N_RB];
    __shared__ int scnt[N_RB];
    const int b    = threadIdx.x;          // 256 threads = 8 warps
    const int wrp  = b >> 5;
    const int lane = b & 31;
    // zero histograms
    for (int t = b; t < 8 * N_RB; t += THREADS) ((int*)whist)[t] = 0;
    __syncthreads();

    const int rb = brow[b];
    const unsigned mask = __match_any_sync(0xffffffffu, rb);
    const int lane_pos = __popc(mask & ((1u << lane) - 1u));
    if (lane_pos == 0) whist[wrp][rb] = __popc(mask);   // leader writes count
    __syncthreads();

    int pos = lane_pos;
    for (int w2 = 0; w2 < wrp; ++w2) pos += whist[w2][rb];
    g_blk[rb][pos] = b;
    g_col[rb][pos] = bcol[b];

    if (b < N_RB) {
        int c = 0;
#pragma unroll
        for (int w2 = 0; w2 < 8; ++w2) c += whist[w2][b];
        g_cnt[b] = c;
        scnt[b] = c;
    }
    __syncthreads();
    if (b < N_RB) {
        int rank = 0;
        for (int j = 0; j < N_RB; ++j)
            rank += (scnt[j] > scnt[b]) || (scnt[j] == scnt[b] && j < b);
        g_rbmap[rank] = b;
    }
}

// pack two floats -> fp16x2, LOWER-k element in LOW half.
__device__ __forceinline__ unsigned pack_f16(float hi, float lo) {
    unsigned d;
    asm("cvt.rn.f16x2.f32 %0, %1, %2;" : "=r"(d) : "f"(hi), "f"(lo));
    return d;
}

// ---- prep: round + fragment-pack W (single fp16 term) ----
__global__ void spmm_quantw_kernel(const float* __restrict__ w) {
    const int b   = blockIdx.x;
    const int tid = threadIdx.x;        // 256 threads: one (s,nt,lane) each
    const int s    = tid >> 7;
    const int nt   = (tid >> 5) & 3;
    const int lane = tid & 31;
    const int g    = lane >> 2;
    const int c    = lane & 3;
    // fragment: n-col = nt*8+g, phys cols 16s + 4c .. 4c+3
    const float4 f = *(const float4*)
        (w + (size_t)b * (BH * BW) + (nt * 8 + g) * BW + 16 * s + 4 * c);
    g_wq[((b * 2 + s) * 4 + nt) * 32 + lane] =
        make_uint2(pack_f16(f.y, f.x), pack_f16(f.w, f.z));
}

__device__ __forceinline__ void mma_f16(float* d, const unsigned* a,
                                        unsigned b0, unsigned b1) {
    asm volatile(
        "mma.sync.aligned.m16n8k16.row.col.f32.f16.f16.f32 "
        "{%0,%1,%2,%3}, {%4,%5,%6,%7}, {%8,%9}, {%0,%1,%2,%3};"
        : "+f"(d[0]), "+f"(d[1]), "+f"(d[2]), "+f"(d[3])
        : "r"(a[0]), "r"(a[1]), "r"(a[2]), "r"(a[3]), "r"(b0), "r"(b1));
}

// ---- main: CTA = 256 tokens x one 32-wide row-block; 8 independent warps.
// Single-term fp16: y ~= fp16(a) * fp16(b); dropped residuals ~ 3e-4 rel
// (measured 2.08e-4 for the a-side alone in R12). 16 HMMA/warp-iter.
__global__ __launch_bounds__(THREADS, 2)
void spmm_main_kernel(const float* __restrict__ x,
                      const float* __restrict__ bias,
                      float* __restrict__ out) {
    __shared__ alignas(16) uint2 smB[SMAX * 2 * 4 * 32];   // 48 KB

    const int rb   = g_rbmap[blockIdx.y];
    const int tok0 = blockIdx.x * TOK_TILE;
    const int tid  = threadIdx.x;
    const int wid  = tid >> 5;
    const int lane = tid & 31;
    const int g    = lane >> 2;   // 0..7
    const int c    = lane & 3;    // 0..3

    const int cnt = g_cnt[rb];

    float acc[2][4][4];
#pragma unroll
    for (int mt = 0; mt < 2; ++mt)
#pragma unroll
        for (int nt = 0; nt < 4; ++nt)
#pragma unroll
            for (int r = 0; r < 4; ++r) acc[mt][nt][r] = 0.0f;

    const float* xw = x + (size_t)(tok0 + wid * 32) * IN_F;

    int done = 0;
    while (done < cnt) {
        const int n = (cnt - done < SMAX) ? (cnt - done) : SMAX;

        __syncthreads();   // previous chunk fully consumed
        for (int t = tid; t < n * 256; t += THREADS) {
            const int ii = t >> 8;
            const int r  = t & 255;
            smB[ii * 256 + r] = g_wq[g_blk[rb][done + ii] * 256 + r];
        }
        __syncthreads();

        int li = (wid + (int)blockIdx.x) % n;
        for (int step = 0; step < n; ++step) {
            const float* xb = xw + g_col[rb][done + li] * BW;

            // A: 8 batched LDG.128; rows mt*16 + 8a + g, cols 16s + 4c
            float4 q[2][2][2];   // [mt][rowhalf a][s]
#pragma unroll
            for (int mt = 0; mt < 2; ++mt)
#pragma unroll
                for (int a = 0; a < 2; ++a)
#pragma unroll
                    for (int s = 0; s < 2; ++s)
                        q[mt][a][s] = *(const float4*)
                            (xb + (size_t)(mt * 16 + 8 * a + g) * IN_F + 16 * s + 4 * c);

#pragma unroll
            for (int s = 0; s < 2; ++s) {
                unsigned am[2][4];
#pragma unroll
                for (int mt = 0; mt < 2; ++mt) {
                    am[mt][0] = pack_f16(q[mt][0][s].y, q[mt][0][s].x);
                    am[mt][1] = pack_f16(q[mt][1][s].y, q[mt][1][s].x);
                    am[mt][2] = pack_f16(q[mt][0][s].w, q[mt][0][s].z);
                    am[mt][3] = pack_f16(q[mt][1][s].w, q[mt][1][s].z);
                }
                uint2 bv[4];
#pragma unroll
                for (int nt = 0; nt < 4; ++nt)
                    bv[nt] = smB[((li * 2 + s) * 4 + nt) * 32 + lane];

#pragma unroll
                for (int nt = 0; nt < 4; ++nt)
#pragma unroll
                    for (int mt = 0; mt < 2; ++mt)
                        mma_f16(acc[mt][nt], am[mt], bv[nt].x, bv[nt].y);
            }

            if (++li == n) li = 0;
        }
        done += n;
    }

    // ---- epilogue: add bias, store ----
    const float* bp = bias + rb * BH;
#pragma unroll
    for (int nt = 0; nt < 4; ++nt) {
        const float2 bv = *(const float2*)(bp + nt * 8 + 2 * c);
#pragma unroll
        for (int mt = 0; mt < 2; ++mt) {
            const int row0 = tok0 + wid * 32 + mt * 16 + g;
            float2 o0, o1;
            o0.x = acc[mt][nt][0] + bv.x;
            o0.y = acc[mt][nt][1] + bv.y;
            o1.x = acc[mt][nt][2] + bv.x;
            o1.y = acc[mt][nt][3] + bv.y;
            *(float2*)(out + (size_t)row0       * OUT_F + rb * BH + nt * 8 + 2 * c) = o0;
            *(float2*)(out + (size_t)(row0 + 8) * OUT_F + rb * BH + nt * 8 + 2 * c) = o1;
        }
    }
}

extern "C" void kernel_launch(void* const* d_in, const int* in_sizes, int n_in,
                              void* d_out, int out_size) {
    (void)in_sizes; (void)n_in; (void)out_size;
    const float* x    = (const float*)d_in[0];
    const float* w    = (const float*)d_in[1];
    const float* bias = (const float*)d_in[2];
    const int*   brow = (const int*)d_in[3];
    const int*   bcol = (const int*)d_in[4];
    float* out = (float*)d_out;

    spmm_prep_kernel<<<1, NB>>>(brow, bcol);
    spmm_quantw_kernel<<<NB, 256>>>(w);
    dim3 grid(N_TOKENS / TOK_TILE, N_RB);
    spmm_main_kernel<<<grid, THREADS>>>(x, bias, out);
}

// round 14
// speedup vs baseline: 3.2384x; 1.1457x over previous
#include <cuda_runtime.h>
#include <cuda_fp16.h>
#include <cstdint>
#include <cstddef>

#define N_TOKENS   16384
#define IN_F       1024
#define OUT_F      1024
#define BH         32
#define BW         32
#define NB         256
#define N_RB       (OUT_F / BH)   // 32
#define N_TG       (N_TOKENS / 32) // 512 token groups
#define N_CB       (IN_F / 32)     // 32 col blocks
#define TOK_TILE   256
#define THREADS    256
#define SMAX       24             // W blocks per smem chunk (48KB of uint2 frags)
#define QX_BLOCKS  (N_TG * N_CB / 8)   // 2048 blocks of 8 warps for quantx

__device__ int g_cnt[N_RB];
__device__ int g_blk[N_RB][NB];
__device__ int g_col[N_RB][NB];
__device__ int g_rbmap[N_RB];
// W fragments: [b][s][nt][lane] = uint2{bm0, bm1} (fp16x2), 512KB
__device__ uint2 g_wq[NB * 2 * 4 * 32];
// x fragments, fragment-major: [unit = tg*32+cb][chunk = s*2+mt][lane] = uint4
// holding the 4 A-regs of (s, mt) for this lane. 32 MB.
__device__ uint4 g_xq[N_TG * N_CB * 4 * 32];

// pack two floats -> fp16x2, LOWER-k element in LOW half.
__device__ __forceinline__ unsigned pack_f16(float hi, float lo) {
    unsigned d;
    asm("cvt.rn.f16x2.f32 %0, %1, %2;" : "=r"(d) : "f"(hi), "f"(lo));
    return d;
}

// ---- fused prepare: quantx (blocks 0..2047) + quantw (2048..2303) + prep (2304) ----
__global__ void spmm_prepare_kernel(const float* __restrict__ x,
                                    const float* __restrict__ w,
                                    const int* __restrict__ brow,
                                    const int* __restrict__ bcol) {
    const int bid = blockIdx.x;
    const int tid = threadIdx.x;

    if (bid < QX_BLOCKS) {
        // ---- quantx: one warp per (tg, cb) unit; write fragment-major fp16 ----
        const int wrp  = tid >> 5;
        const int lane = tid & 31;
        const int unit = bid * 8 + wrp;
        const int tg   = unit >> 5;          // token group 0..511
        const int cb   = unit & 31;          // col block 0..31
        const int g    = lane >> 2;
        const int c    = lane & 3;
        const float* xb = x + (size_t)(tg * 32) * IN_F + cb * 32;
#pragma unroll
        for (int s = 0; s < 2; ++s)
#pragma unroll
            for (int mt = 0; mt < 2; ++mt) {
                const float4 A0 = *(const float4*)(xb + (size_t)(mt * 16 + g)     * IN_F + 16 * s + 4 * c);
                const float4 A1 = *(const float4*)(xb + (size_t)(mt * 16 + 8 + g) * IN_F + 16 * s + 4 * c);
                g_xq[(unit * 4 + (s * 2 + mt)) * 32 + lane] =
                    make_uint4(pack_f16(A0.y, A0.x), pack_f16(A1.y, A1.x),
                               pack_f16(A0.w, A0.z), pack_f16(A1.w, A1.z));
            }
    } else if (bid < QX_BLOCKS + NB) {
        // ---- quantw: round + fragment-pack one W block ----
        const int b    = bid - QX_BLOCKS;
        const int s    = tid >> 7;
        const int nt   = (tid >> 5) & 3;
        const int lane = tid & 31;
        const int g    = lane >> 2;
        const int c    = lane & 3;
        const float4 f = *(const float4*)
            (w + (size_t)b * (BH * BW) + (nt * 8 + g) * BW + 16 * s + 4 * c);
        g_wq[((b * 2 + s) * 4 + nt) * 32 + lane] =
            make_uint2(pack_f16(f.y, f.x), pack_f16(f.w, f.z));
    } else {
        // ---- prep: ballot-based stable compaction + LPT sort (one block) ----
        __shared__ int whist[8][N_RB];
        __shared__ int scnt[N_RB];
        const int b    = tid;
        const int wrp  = b >> 5;
        const int lane = b & 31;
        for (int t = b; t < 8 * N_RB; t += THREADS) ((int*)whist)[t] = 0;
        __syncthreads();
        const int rb = brow[b];
        const unsigned mask = __match_any_sync(0xffffffffu, rb);
        const int lane_pos = __popc(mask & ((1u << lane) - 1u));
        if (lane_pos == 0) whist[wrp][rb] = __popc(mask);
        __syncthreads();
        int pos = lane_pos;
        for (int w2 = 0; w2 < wrp; ++w2) pos += whist[w2][rb];
        g_blk[rb][pos] = b;
        g_col[rb][pos] = bcol[b];
        if (b < N_RB) {
            int cc = 0;
#pragma unroll
            for (int w2 = 0; w2 < 8; ++w2) cc += whist[w2][b];
            g_cnt[b] = cc;
            scnt[b] = cc;
        }
        __syncthreads();
        if (b < N_RB) {
            int rank = 0;
            for (int j = 0; j < N_RB; ++j)
                rank += (scnt[j] > scnt[b]) || (scnt[j] == scnt[b] && j < b);
            g_rbmap[rank] = b;
        }
    }
}

__device__ __forceinline__ void mma_f16(float* d, const unsigned* a,
                                        unsigned b0, unsigned b1) {
    asm volatile(
        "mma.sync.aligned.m16n8k16.row.col.f32.f16.f16.f32 "
        "{%0,%1,%2,%3}, {%4,%5,%6,%7}, {%8,%9}, {%0,%1,%2,%3};"
        : "+f"(d[0]), "+f"(d[1]), "+f"(d[2]), "+f"(d[3])
        : "r"(a[0]), "r"(a[1]), "r"(a[2]), "r"(a[3]), "r"(b0), "r"(b1));
}

// ---- main: CTA = 256 tokens x one 32-wide row-block; 8 independent warps.
// Single-term fp16 (rel ~3e-4). A comes from fragment-major g_xq: 4 coalesced
// LDG.128 per warp-iter (16 L1 wavefronts vs 64 for row-major fp32); no in-loop
// cvt. W fragments from smem chunks. 16 HMMA/warp-iter.
__global__ __launch_bounds__(THREADS, 2)
void spmm_main_kernel(const float* __restrict__ bias,
                      float* __restrict__ out) {
    __shared__ alignas(16) uint2 smB[SMAX * 2 * 4 * 32];   // 48 KB

    const int rb   = g_rbmap[blockIdx.y];
    const int tok0 = blockIdx.x * TOK_TILE;
    const int tid  = threadIdx.x;
    const int wid  = tid >> 5;
    const int lane = tid & 31;
    const int g    = lane >> 2;   // 0..7
    const int c    = lane & 3;    // 0..3
    const int tgw  = blockIdx.x * 8 + wid;   // this warp's token group

    const int cnt = g_cnt[rb];

    float acc[2][4][4];
#pragma unroll
    for (int mt = 0; mt < 2; ++mt)
#pragma unroll
        for (int nt = 0; nt < 4; ++nt)
#pragma unroll
            for (int r = 0; r < 4; ++r) acc[mt][nt][r] = 0.0f;

    int done = 0;
    while (done < cnt) {
        const int n = (cnt - done < SMAX) ? (cnt - done) : SMAX;

        __syncthreads();   // previous chunk fully consumed
        for (int t = tid; t < n * 256; t += THREADS) {
            const int ii = t >> 8;
            const int r  = t & 255;
            smB[ii * 256 + r] = g_wq[g_blk[rb][done + ii] * 256 + r];
        }
        __syncthreads();

        int li = (wid + (int)blockIdx.x) % n;
        for (int step = 0; step < n; ++step) {
            const int cb = g_col[rb][done + li];

            // A: 4 coalesced LDG.128 of pre-packed fragments
            const uint4* ap = &g_xq[(size_t)(tgw * N_CB + cb) * 4 * 32 + lane];
            const uint4 q0 = ap[0];     // (s0, mt0)
            const uint4 q1 = ap[32];    // (s0, mt1)
            const uint4 q2 = ap[64];    // (s1, mt0)
            const uint4 q3 = ap[96];    // (s1, mt1)
            const unsigned* aq[2][2] = { { (const unsigned*)&q0, (const unsigned*)&q1 },
                                         { (const unsigned*)&q2, (const unsigned*)&q3 } };

#pragma unroll
            for (int s = 0; s < 2; ++s) {
                uint2 bv[4];
#pragma unroll
                for (int nt = 0; nt < 4; ++nt)
                    bv[nt] = smB[((li * 2 + s) * 4 + nt) * 32 + lane];
#pragma unroll
                for (int nt = 0; nt < 4; ++nt)
#pragma unroll
                    for (int mt = 0; mt < 2; ++mt)
                        mma_f16(acc[mt][nt], aq[s][mt], bv[nt].x, bv[nt].y);
            }

            if (++li == n) li = 0;
        }
        done += n;
    }

    // ---- epilogue: add bias, store ----
    const float* bp = bias + rb * BH;
#pragma unroll
    for (int nt = 0; nt < 4; ++nt) {
        const float2 bv = *(const float2*)(bp + nt * 8 + 2 * c);
#pragma unroll
        for (int mt = 0; mt < 2; ++mt) {
            const int row0 = tok0 + wid * 32 + mt * 16 + g;
            float2 o0, o1;
            o0.x = acc[mt][nt][0] + bv.x;
            o0.y = acc[mt][nt][1] + bv.y;
            o1.x = acc[mt][nt][2] + bv.x;
            o1.y = acc[mt][nt][3] + bv.y;
            *(float2*)(out + (size_t)row0       * OUT_F + rb * BH + nt * 8 + 2 * c) = o0;
            *(float2*)(out + (size_t)(row0 + 8) * OUT_F + rb * BH + nt * 8 + 2 * c) = o1;
        }
    }
}

extern "C" void kernel_launch(void* const* d_in, const int* in_sizes, int n_in,
                              void* d_out, int out_size) {
    (void)in_sizes; (void)n_in; (void)out_size;
    const float* x    = (const float*)d_in[0];
    const float* w    = (const float*)d_in[1];
    const float* bias = (const float*)d_in[2];
    const int*   brow = (const int*)d_in[3];
    const int*   bcol = (const int*)d_in[4];
    float* out = (float*)d_out;

    spmm_prepare_kernel<<<QX_BLOCKS + NB + 1, THREADS>>>(x, w, brow, bcol);
    dim3 grid(N_TOKENS / TOK_TILE, N_RB);
    spmm_main_kernel<<<grid, THREADS>>>(bias, out);
}

// round 15
// speedup vs baseline: 3.3678x; 1.0399x over previous
#include <cuda_runtime.h>
#include <cuda_fp16.h>
#include <cstdint>
#include <cstddef>

#define N_TOKENS   16384
#define IN_F       1024
#define OUT_F      1024
#define BH         32
#define BW         32
#define NB         256
#define N_RB       (OUT_F / BH)   // 32
#define N_TG       (N_TOKENS / 32) // 512 token groups
#define N_CB       (IN_F / 32)     // 32 col blocks
#define TOK_TILE   256
#define THREADS    256
#define SMAX       24             // W blocks per smem chunk (48KB of uint2 frags)
#define QX_BLOCKS  (N_TG * N_CB / 8)   // 2048 blocks of 8 warps for quantx

__device__ int g_cnt[N_RB];
__device__ int g_blk[N_RB][NB];
__device__ int g_col[N_RB][NB];
__device__ int g_rbmap[N_RB];
// W fragments: [b][s][nt][lane] = uint2{bm0, bm1} (fp16x2), 512KB
__device__ uint2 g_wq[NB * 2 * 4 * 32];
// x fragments, fragment-major: [unit = tg*32+cb][chunk = s*2+mt][lane] = uint4
__device__ uint4 g_xq[N_TG * N_CB * 4 * 32];   // 32 MB

// pack two floats -> fp16x2, LOWER-k element in LOW half.
__device__ __forceinline__ unsigned pack_f16(float hi, float lo) {
    unsigned d;
    asm("cvt.rn.f16x2.f32 %0, %1, %2;" : "=r"(d) : "f"(hi), "f"(lo));
    return d;
}

// ---- fused prepare: quantx (blocks 0..2047) + quantw (2048..2303) + prep (2304) ----
__global__ void spmm_prepare_kernel(const float* __restrict__ x,
                                    const float* __restrict__ w,
                                    const int* __restrict__ brow,
                                    const int* __restrict__ bcol) {
    const int bid = blockIdx.x;
    const int tid = threadIdx.x;

    if (bid < QX_BLOCKS) {
        // ---- quantx: one warp per (tg, cb) unit; write fragment-major fp16 ----
        const int wrp  = tid >> 5;
        const int lane = tid & 31;
        const int unit = bid * 8 + wrp;
        const int tg   = unit >> 5;
        const int cb   = unit & 31;
        const int g    = lane >> 2;
        const int c    = lane & 3;
        const float* xb = x + (size_t)(tg * 32) * IN_F + cb * 32;
#pragma unroll
        for (int s = 0; s < 2; ++s)
#pragma unroll
            for (int mt = 0; mt < 2; ++mt) {
                const float4 A0 = *(const float4*)(xb + (size_t)(mt * 16 + g)     * IN_F + 16 * s + 4 * c);
                const float4 A1 = *(const float4*)(xb + (size_t)(mt * 16 + 8 + g) * IN_F + 16 * s + 4 * c);
                g_xq[(unit * 4 + (s * 2 + mt)) * 32 + lane] =
                    make_uint4(pack_f16(A0.y, A0.x), pack_f16(A1.y, A1.x),
                               pack_f16(A0.w, A0.z), pack_f16(A1.w, A1.z));
            }
    } else if (bid < QX_BLOCKS + NB) {
        // ---- quantw: round + fragment-pack one W block ----
        const int b    = bid - QX_BLOCKS;
        const int s    = tid >> 7;
        const int nt   = (tid >> 5) & 3;
        const int lane = tid & 31;
        const int g    = lane >> 2;
        const int c    = lane & 3;
        const float4 f = *(const float4*)
            (w + (size_t)b * (BH * BW) + (nt * 8 + g) * BW + 16 * s + 4 * c);
        g_wq[((b * 2 + s) * 4 + nt) * 32 + lane] =
            make_uint2(pack_f16(f.y, f.x), pack_f16(f.w, f.z));
    } else {
        // ---- prep: ballot-based stable compaction + LPT sort (one block) ----
        __shared__ int whist[8][N_RB];
        __shared__ int scnt[N_RB];
        const int b    = tid;
        const int wrp  = b >> 5;
        const int lane = b & 31;
        for (int t = b; t < 8 * N_RB; t += THREADS) ((int*)whist)[t] = 0;
        __syncthreads();
        const int rb = brow[b];
        const unsigned mask = __match_any_sync(0xffffffffu, rb);
        const int lane_pos = __popc(mask & ((1u << lane) - 1u));
        if (lane_pos == 0) whist[wrp][rb] = __popc(mask);
        __syncthreads();
        int pos = lane_pos;
        for (int w2 = 0; w2 < wrp; ++w2) pos += whist[w2][rb];
        g_blk[rb][pos] = b;
        g_col[rb][pos] = bcol[b];
        if (b < N_RB) {
            int cc = 0;
#pragma unroll
            for (int w2 = 0; w2 < 8; ++w2) cc += whist[w2][b];
            g_cnt[b] = cc;
            scnt[b] = cc;
        }
        __syncthreads();
        if (b < N_RB) {
            int rank = 0;
            for (int j = 0; j < N_RB; ++j)
                rank += (scnt[j] > scnt[b]) || (scnt[j] == scnt[b] && j < b);
            g_rbmap[rank] = b;
        }
    }
}

__device__ __forceinline__ void mma_f16(float* d, const unsigned* a,
                                        unsigned b0, unsigned b1) {
    asm volatile(
        "mma.sync.aligned.m16n8k16.row.col.f32.f16.f16.f32 "
        "{%0,%1,%2,%3}, {%4,%5,%6,%7}, {%8,%9}, {%0,%1,%2,%3};"
        : "+f"(d[0]), "+f"(d[1]), "+f"(d[2]), "+f"(d[3])
        : "r"(a[0]), "r"(a[1]), "r"(a[2]), "r"(a[3]), "r"(b0), "r"(b1));
}

// ---- main: CTA = 256 tokens x one 32-wide row-block; 8 independent warps.
// Single-term fp16 (rel ~3e-4). A from fragment-major g_xq via 4 coalesced
// LDG.128, PING-PONG PREFETCHED one iteration ahead so the L2 round-trip
// hides under the previous iteration's 16 HMMAs.
__global__ __launch_bounds__(THREADS, 2)
void spmm_main_kernel(const float* __restrict__ bias,
                      float* __restrict__ out) {
    __shared__ alignas(16) uint2 smB[SMAX * 2 * 4 * 32];   // 48 KB

    const int rb   = g_rbmap[blockIdx.y];
    const int tok0 = blockIdx.x * TOK_TILE;
    const int tid  = threadIdx.x;
    const int wid  = tid >> 5;
    const int lane = tid & 31;
    const int g    = lane >> 2;   // 0..7
    const int c    = lane & 3;    // 0..3
    const int tgw  = blockIdx.x * 8 + wid;   // this warp's token group

    const int cnt = g_cnt[rb];

    float acc[2][4][4];
#pragma unroll
    for (int mt = 0; mt < 2; ++mt)
#pragma unroll
        for (int nt = 0; nt < 4; ++nt)
#pragma unroll
            for (int r = 0; r < 4; ++r) acc[mt][nt][r] = 0.0f;

    const uint4* xqw = &g_xq[(size_t)tgw * N_CB * 4 * 32 + lane];

    uint4 qa[4], qb[4];   // ping-pong A fragment buffers (16 regs each)

    auto load_q = [&](uint4* q, int gi) {
        const uint4* ap = xqw + (size_t)g_col[rb][gi] * 128;
        q[0] = ap[0];
        q[1] = ap[32];
        q[2] = ap[64];
        q[3] = ap[96];
    };
    auto compute = [&](const uint4* q, int li) {
#pragma unroll
        for (int s = 0; s < 2; ++s) {
            uint2 bv[4];
#pragma unroll
            for (int nt = 0; nt < 4; ++nt)
                bv[nt] = smB[((li * 2 + s) * 4 + nt) * 32 + lane];
#pragma unroll
            for (int nt = 0; nt < 4; ++nt)
#pragma unroll
                for (int mt = 0; mt < 2; ++mt)
                    mma_f16(acc[mt][nt], (const unsigned*)&q[s * 2 + mt],
                            bv[nt].x, bv[nt].y);
        }
    };

    int done = 0;
    while (done < cnt) {
        const int n = (cnt - done < SMAX) ? (cnt - done) : SMAX;

        __syncthreads();   // previous chunk fully consumed
        for (int t = tid; t < n * 256; t += THREADS) {
            const int ii = t >> 8;
            const int r  = t & 255;
            smB[ii * 256 + r] = g_wq[g_blk[rb][done + ii] * 256 + r];
        }
        __syncthreads();

        // rotated walk with register ping-pong prefetch
        int li = (wid + (int)blockIdx.x) % n;
        int nli = li;
        auto advance = [&](int v) { return (v + 1 == n) ? 0 : v + 1; };

        load_q(qa, done + li);
        int step = 0;
        while (true) {
            if (step + 1 < n) { nli = advance(li); load_q(qb, done + nli); }
            compute(qa, li);
            if (++step >= n) break;
            li = nli;
            if (step + 1 < n) { nli = advance(li); load_q(qa, done + nli); }
            compute(qb, li);
            if (++step >= n) break;
            li = nli;
        }
        done += n;
    }

    // ---- epilogue: add bias, store ----
    const float* bp = bias + rb * BH;
#pragma unroll
    for (int nt = 0; nt < 4; ++nt) {
        const float2 bv = *(const float2*)(bp + nt * 8 + 2 * c);
#pragma unroll
        for (int mt = 0; mt < 2; ++mt) {
            const int row0 = tok0 + wid * 32 + mt * 16 + g;
            float2 o0, o1;
            o0.x = acc[mt][nt][0] + bv.x;
            o0.y = acc[mt][nt][1] + bv.y;
            o1.x = acc[mt][nt][2] + bv.x;
            o1.y = acc[mt][nt][3] + bv.y;
            *(float2*)(out + (size_t)row0       * OUT_F + rb * BH + nt * 8 + 2 * c) = o0;
            *(float2*)(out + (size_t)(row0 + 8) * OUT_F + rb * BH + nt * 8 + 2 * c) = o1;
        }
    }
}

extern "C" void kernel_launch(void* const* d_in, const int* in_sizes, int n_in,
                              void* d_out, int out_size) {
    (void)in_sizes; (void)n_in; (void)out_size;
    const float* x    = (const float*)d_in[0];
    const float* w    = (const float*)d_in[1];
    const float* bias = (const float*)d_in[2];
    const int*   brow = (const int*)d_in[3];
    const int*   bcol = (const int*)d_in[4];
    float* out = (float*)d_out;

    spmm_prepare_kernel<<<QX_BLOCKS + NB + 1, THREADS>>>(x, w, brow, bcol);
    dim3 grid(N_TOKENS / TOK_TILE, N_RB);
    spmm_main_kernel<<<grid, THREADS>>>(bias, out);
}

// round 16
// speedup vs baseline: 3.8073x; 1.1305x over previous
#include <cuda_runtime.h>
#include <cuda_fp16.h>
#include <cstdint>
#include <cstddef>

#define N_TOKENS   16384
#define IN_F       1024
#define OUT_F      1024
#define BH         32
#define BW         32
#define NB         256
#define N_RB       (OUT_F / BH)   // 32
#define N_TG       (N_TOKENS / 32) // 512 token groups
#define N_CB       (IN_F / 32)     // 32 col blocks
#define TOK_TILE   256
#define THREADS    256
#define SMAX       24             // W blocks per smem chunk (48KB of uint2 frags)
#define QX_BLOCKS  (N_TG * N_CB / 8)   // 2048 blocks of 8 warps for quantx

__device__ int g_cnt[N_RB];
__device__ int g_blk[N_RB][NB];
__device__ int g_col[N_RB][NB];
__device__ int g_rbmap[N_RB];
// W fragments: [b][s][nt][lane] = uint2{bm0, bm1} (fp16x2), 512KB
__device__ uint2 g_wq[NB * 2 * 4 * 32];
// x fragments, fragment-major: [unit = tg*32+cb][chunk = s*2+mt][lane] = uint4
__device__ uint4 g_xq[N_TG * N_CB * 4 * 32];   // 32 MB

// pack two floats -> fp16x2, LOWER-k element in LOW half.
__device__ __forceinline__ unsigned pack_f16(float hi, float lo) {
    unsigned d;
    asm("cvt.rn.f16x2.f32 %0, %1, %2;" : "=r"(d) : "f"(hi), "f"(lo));
    return d;
}

// ---- fused prepare: quantx (blocks 0..2047) + quantw (2048..2303) + prep (2304) ----
__global__ void spmm_prepare_kernel(const float* __restrict__ x,
                                    const float* __restrict__ w,
                                    const int* __restrict__ brow,
                                    const int* __restrict__ bcol) {
    const int bid = blockIdx.x;
    const int tid = threadIdx.x;

    if (bid < QX_BLOCKS) {
        // ---- quantx: one warp per (tg, cb) unit; write fragment-major fp16 ----
        const int wrp  = tid >> 5;
        const int lane = tid & 31;
        const int unit = bid * 8 + wrp;
        const int tg   = unit >> 5;
        const int cb   = unit & 31;
        const int g    = lane >> 2;
        const int c    = lane & 3;
        const float* xb = x + (size_t)(tg * 32) * IN_F + cb * 32;
#pragma unroll
        for (int s = 0; s < 2; ++s)
#pragma unroll
            for (int mt = 0; mt < 2; ++mt) {
                const float4 A0 = *(const float4*)(xb + (size_t)(mt * 16 + g)     * IN_F + 16 * s + 4 * c);
                const float4 A1 = *(const float4*)(xb + (size_t)(mt * 16 + 8 + g) * IN_F + 16 * s + 4 * c);
                g_xq[(unit * 4 + (s * 2 + mt)) * 32 + lane] =
                    make_uint4(pack_f16(A0.y, A0.x), pack_f16(A1.y, A1.x),
                               pack_f16(A0.w, A0.z), pack_f16(A1.w, A1.z));
            }
    } else if (bid < QX_BLOCKS + NB) {
        // ---- quantw: round + fragment-pack one W block ----
        const int b    = bid - QX_BLOCKS;
        const int s    = tid >> 7;
        const int nt   = (tid >> 5) & 3;
        const int lane = tid & 31;
        const int g    = lane >> 2;
        const int c    = lane & 3;
        const float4 f = *(const float4*)
            (w + (size_t)b * (BH * BW) + (nt * 8 + g) * BW + 16 * s + 4 * c);
        g_wq[((b * 2 + s) * 4 + nt) * 32 + lane] =
            make_uint2(pack_f16(f.y, f.x), pack_f16(f.w, f.z));
    } else {
        // ---- prep: ballot-based stable compaction + LPT sort (one block) ----
        __shared__ int whist[8][N_RB];
        __shared__ int scnt[N_RB];
        const int b    = tid;
        const int wrp  = b >> 5;
        const int lane = b & 31;
        for (int t = b; t < 8 * N_RB; t += THREADS) ((int*)whist)[t] = 0;
        __syncthreads();
        const int rb = brow[b];
        const unsigned mask = __match_any_sync(0xffffffffu, rb);
        const int lane_pos = __popc(mask & ((1u << lane) - 1u));
        if (lane_pos == 0) whist[wrp][rb] = __popc(mask);
        __syncthreads();
        int pos = lane_pos;
        for (int w2 = 0; w2 < wrp; ++w2) pos += whist[w2][rb];
        g_blk[rb][pos] = b;
        g_col[rb][pos] = bcol[b];
        if (b < N_RB) {
            int cc = 0;
#pragma unroll
            for (int w2 = 0; w2 < 8; ++w2) cc += whist[w2][b];
            g_cnt[b] = cc;
            scnt[b] = cc;
        }
        __syncthreads();
        if (b < N_RB) {
            int rank = 0;
            for (int j = 0; j < N_RB; ++j)
                rank += (scnt[j] > scnt[b]) || (scnt[j] == scnt[b] && j < b);
            g_rbmap[rank] = b;
        }
    }
}

__device__ __forceinline__ void mma_f16(float* d, const unsigned* a,
                                        unsigned b0, unsigned b1) {
    asm volatile(
        "mma.sync.aligned.m16n8k16.row.col.f32.f16.f16.f32 "
        "{%0,%1,%2,%3}, {%4,%5,%6,%7}, {%8,%9}, {%0,%1,%2,%3};"
        : "+f"(d[0]), "+f"(d[1]), "+f"(d[2]), "+f"(d[3])
        : "r"(a[0]), "r"(a[1]), "r"(a[2]), "r"(a[3]), "r"(b0), "r"(b1));
}

// ---- main: CTA = 256 tokens x one 32-wide row-block; 8 independent warps.
// Single-term fp16 (rel ~3e-4). A from fragment-major g_xq (4 coalesced
// LDG.128/iter). Latency hidden by 3-CTA occupancy (24 warps/SM, 6/SMSP)
// instead of register ping-pong (which costs too many regs at bound 3).
__global__ __launch_bounds__(THREADS, 3)
void spmm_main_kernel(const float* __restrict__ bias,
                      float* __restrict__ out) {
    __shared__ alignas(16) uint2 smB[SMAX * 2 * 4 * 32];   // 48 KB

    const int rb   = g_rbmap[blockIdx.y];
    const int tok0 = blockIdx.x * TOK_TILE;
    const int tid  = threadIdx.x;
    const int wid  = tid >> 5;
    const int lane = tid & 31;
    const int g    = lane >> 2;   // 0..7
    const int c    = lane & 3;    // 0..3
    const int tgw  = blockIdx.x * 8 + wid;   // this warp's token group

    const int cnt = g_cnt[rb];

    float acc[2][4][4];
#pragma unroll
    for (int mt = 0; mt < 2; ++mt)
#pragma unroll
        for (int nt = 0; nt < 4; ++nt)
#pragma unroll
            for (int r = 0; r < 4; ++r) acc[mt][nt][r] = 0.0f;

    const uint4* xqw = &g_xq[(size_t)tgw * N_CB * 4 * 32 + lane];

    int done = 0;
    while (done < cnt) {
        const int n = (cnt - done < SMAX) ? (cnt - done) : SMAX;

        __syncthreads();   // previous chunk fully consumed
        for (int t = tid; t < n * 256; t += THREADS) {
            const int ii = t >> 8;
            const int r  = t & 255;
            smB[ii * 256 + r] = g_wq[g_blk[rb][done + ii] * 256 + r];
        }
        __syncthreads();

        int li = (wid + (int)blockIdx.x) % n;
        for (int step = 0; step < n; ++step) {
            const uint4* ap = xqw + (size_t)g_col[rb][done + li] * 128;

            // A: 4 coalesced LDG.128 (batched, MLP=4)
            const uint4 q0 = ap[0];     // (s0, mt0)
            const uint4 q1 = ap[32];    // (s0, mt1)
            const uint4 q2 = ap[64];    // (s1, mt0)
            const uint4 q3 = ap[96];    // (s1, mt1)

            // B: batch all 8 LDS.64 up front (one latency exposure)
            uint2 bv[2][4];
#pragma unroll
            for (int s = 0; s < 2; ++s)
#pragma unroll
                for (int nt = 0; nt < 4; ++nt)
                    bv[s][nt] = smB[((li * 2 + s) * 4 + nt) * 32 + lane];

#pragma unroll
            for (int nt = 0; nt < 4; ++nt) {
                mma_f16(acc[0][nt], (const unsigned*)&q0, bv[0][nt].x, bv[0][nt].y);
                mma_f16(acc[1][nt], (const unsigned*)&q1, bv[0][nt].x, bv[0][nt].y);
            }
#pragma unroll
            for (int nt = 0; nt < 4; ++nt) {
                mma_f16(acc[0][nt], (const unsigned*)&q2, bv[1][nt].x, bv[1][nt].y);
                mma_f16(acc[1][nt], (const unsigned*)&q3, bv[1][nt].x, bv[1][nt].y);
            }

            if (++li == n) li = 0;
        }
        done += n;
    }

    // ---- epilogue: add bias, store ----
    const float* bp = bias + rb * BH;
#pragma unroll
    for (int nt = 0; nt < 4; ++nt) {
        const float2 bv = *(const float2*)(bp + nt * 8 + 2 * c);
#pragma unroll
        for (int mt = 0; mt < 2; ++mt) {
            const int row0 = tok0 + wid * 32 + mt * 16 + g;
            float2 o0, o1;
            o0.x = acc[mt][nt][0] + bv.x;
            o0.y = acc[mt][nt][1] + bv.y;
            o1.x = acc[mt][nt][2] + bv.x;
            o1.y = acc[mt][nt][3] + bv.y;
            *(float2*)(out + (size_t)row0       * OUT_F + rb * BH + nt * 8 + 2 * c) = o0;
            *(float2*)(out + (size_t)(row0 + 8) * OUT_F + rb * BH + nt * 8 + 2 * c) = o1;
        }
    }
}

extern "C" void kernel_launch(void* const* d_in, const int* in_sizes, int n_in,
                              void* d_out, int out_size) {
    (void)in_sizes; (void)n_in; (void)out_size;
    const float* x    = (const float*)d_in[0];
    const float* w    = (const float*)d_in[1];
    const float* bias = (const float*)d_in[2];
    const int*   brow = (const int*)d_in[3];
    const int*   bcol = (const int*)d_in[4];
    float* out = (float*)d_out;

    spmm_prepare_kernel<<<QX_BLOCKS + NB + 1, THREADS>>>(x, w, brow, bcol);
    dim3 grid(N_TOKENS / TOK_TILE, N_RB);
    spmm_main_kernel<<<grid, THREADS>>>(bias, out);
}